// round 14
// baseline (speedup 1.0000x reference)
#include <cuda_runtime.h>
#include <cuda_bf16.h>
#include <mma.h>
#include <cstdint>

using namespace nvcuda;

#define Bb 2
#define Ss 2048
#define Ee 1024
#define Hh 16
#define Hd 64

// ------------------------- scratch (__device__ globals) ----------------------
__device__ float g_Q1[Bb * Ss * Hd];
__device__ float g_K1[Bb * Ss * Hd];
__device__ float g_V [Bb * Ss * Ee];     // V projection, flat (b, s, e)
__device__ float g_Vt[Bb * Ee * Ss];     // Vt[b][h*64+d][k] = V[b, h, k, d]
__device__ float g_attn[Bb * Ss * Ee];   // attn in flat (b, h, q, d) layout

// ---------------------------------------------------------------------------
// wmma split-bf16 NT GEMM, 128x128 tile, in-kernel hi/lo split.
// Fragment semantics = validated (A row_major [m][k] p40, B col_major [n][k] p40).
// Epilogue = direct-to-global store_matrix_sync (validated R12), bias staged
// into accumulators via smem (validated R12).
// mode 0: C[m*ldC+n].  mode 1 (BN frag inside one 64-col head): head-flat.
// ---------------------------------------------------------------------------
__global__ void __launch_bounds__(256) wsplit_gemm128(
    const float* __restrict__ A, long Az,
    const float* __restrict__ B, long Bz,
    float* __restrict__ C, long Cz, int ldC,
    const float* __restrict__ bias, int K, int mode)
{
    __shared__ __align__(128) __nv_bfloat16 sAh[128][40];
    __shared__ __align__(128) __nv_bfloat16 sAl[128][40];
    __shared__ __align__(128) __nv_bfloat16 sBh[128][40];
    __shared__ __align__(128) __nv_bfloat16 sBl[128][40];

    const int tid = threadIdx.x, wid = tid >> 5;
    const int wm = wid & 1, wn = wid >> 1;
    const int m0 = blockIdx.y * 128, n0 = blockIdx.x * 128;
    A += (size_t)blockIdx.z * Az;
    B += (size_t)blockIdx.z * Bz;
    C += (size_t)blockIdx.z * Cz;

    wmma::fragment<wmma::accumulator, 16, 16, 16, float> acc[4][2];
    if (bias) {
        // Stage bias (16 rows replicated) in sAh area; init accumulators (R12-validated).
        float* bstage = (float*)sAh;               // 16 x 136 floats
        #pragma unroll
        for (int it = 0; it < 8; ++it) {
            int idx = it * 256 + tid;              // 0..2047
            int r = idx >> 7, c = idx & 127;
            bstage[r * 136 + c] = bias[n0 + c];
        }
        __syncthreads();
        #pragma unroll
        for (int j = 0; j < 2; ++j) {
            wmma::load_matrix_sync(acc[0][j], bstage + wn * 32 + j * 16, 136,
                                   wmma::mem_row_major);
            #pragma unroll
            for (int i = 1; i < 4; ++i) acc[i][j] = acc[0][j];
        }
        __syncthreads();
    } else {
        #pragma unroll
        for (int i = 0; i < 4; ++i)
            #pragma unroll
            for (int j = 0; j < 2; ++j)
                wmma::fill_fragment(acc[i][j], 0.0f);
    }

    // Loader (validated split pattern, 128 rows): row = tid>>1, 16 cols/thread.
    const int lrow = tid >> 1, lcb = (tid & 1) * 16;

    for (int k0 = 0; k0 < K; k0 += 32) {
        const float* ga = A + (size_t)(m0 + lrow) * K + k0 + lcb;
        const float* gb = B + (size_t)(n0 + lrow) * K + k0 + lcb;
        #pragma unroll
        for (int j = 0; j < 16; j += 4) {
            float4 va = *(const float4*)(ga + j);
            float4 vb = *(const float4*)(gb + j);
            float av[4] = {va.x, va.y, va.z, va.w};
            float bv[4] = {vb.x, vb.y, vb.z, vb.w};
            #pragma unroll
            for (int u = 0; u < 4; ++u) {
                __nv_bfloat16 ha = __float2bfloat16(av[u]);
                sAh[lrow][lcb + j + u] = ha;
                sAl[lrow][lcb + j + u] = __float2bfloat16(av[u] - __bfloat162float(ha));
                __nv_bfloat16 hb = __float2bfloat16(bv[u]);
                sBh[lrow][lcb + j + u] = hb;
                sBl[lrow][lcb + j + u] = __float2bfloat16(bv[u] - __bfloat162float(hb));
            }
        }
        __syncthreads();

        #pragma unroll
        for (int p = 0; p < 3; ++p) {
            const __nv_bfloat16 (*aS)[40] = (p == 2) ? sAl : sAh;
            const __nv_bfloat16 (*bS)[40] = (p == 1) ? sBl : sBh;
            #pragma unroll
            for (int kk = 0; kk < 32; kk += 16) {
                wmma::fragment<wmma::matrix_b, 16, 16, 16, __nv_bfloat16, wmma::col_major> bf[2];
                #pragma unroll
                for (int j = 0; j < 2; ++j)
                    wmma::load_matrix_sync(bf[j], &bS[wn * 32 + j * 16][kk], 40);
                #pragma unroll
                for (int i = 0; i < 4; ++i) {
                    wmma::fragment<wmma::matrix_a, 16, 16, 16, __nv_bfloat16, wmma::row_major> af;
                    wmma::load_matrix_sync(af, &aS[wm * 64 + i * 16][kk], 40);
                    #pragma unroll
                    for (int j = 0; j < 2; ++j)
                        wmma::mma_sync(acc[i][j], af, bf[j], acc[i][j]);
                }
            }
        }
        __syncthreads();
    }

    // Direct-to-global epilogue (R12-validated). Each fragment: rows
    // m0+wm*64+i*16 .., cols n0+wn*32+j*16 .. (+16, inside one head for mode 1).
    #pragma unroll
    for (int i = 0; i < 4; ++i) {
        #pragma unroll
        for (int j = 0; j < 2; ++j) {
            const int mrow = m0 + wm * 64 + i * 16;
            const int ncol = n0 + wn * 32 + j * 16;
            if (mode == 0) {
                wmma::store_matrix_sync(&C[(size_t)mrow * ldC + ncol], acc[i][j],
                                        ldC, wmma::mem_row_major);
            } else {
                // Head-flat: h = ncol>>6, d = ncol&63; ld = Hd (frag stays in-head).
                float* base = C + (size_t)(ncol >> 6) * (Ss * Hd)
                                + (size_t)mrow * Hd + (ncol & 63);
                wmma::store_matrix_sync(base, acc[i][j], Hd, wmma::mem_row_major);
            }
        }
    }
}

// ---------------------------------------------------------------------------
// wmma split-bf16 scores (VALIDATED round 13):
// P[q,k] = 0.125 * dot(Q1[q,:], K1[k,:]) - slope*|q-k|
// ---------------------------------------------------------------------------
__global__ void __launch_bounds__(256) wsplit_scores(
    const float* __restrict__ slopes, float* __restrict__ P)
{
    __shared__ __align__(128) __nv_bfloat16 sAh[64][40];
    __shared__ __align__(128) __nv_bfloat16 sAl[64][40];
    __shared__ __align__(128) __nv_bfloat16 sBh[64][40];
    __shared__ __align__(128) __nv_bfloat16 sBl[64][40];
    __shared__ __align__(128) float sC[64][72];

    const int tid = threadIdx.x, wid = tid >> 5;
    const int wm = wid & 1, wn = wid >> 1;
    const int m0 = blockIdx.y * 64, n0 = blockIdx.x * 64;
    const float* A = g_Q1 + (size_t)blockIdx.z * Ss * Hd;
    const float* B = g_K1 + (size_t)blockIdx.z * Ss * Hd;
    float* Pb = P + (size_t)blockIdx.z * Ss * Ss;

    const int lrow = tid >> 2, lcb = (tid & 3) * 8;

    wmma::fragment<wmma::accumulator, 16, 16, 16, float> acc[2];
    wmma::fill_fragment(acc[0], 0.0f);
    wmma::fill_fragment(acc[1], 0.0f);

    for (int k0 = 0; k0 < Hd; k0 += 32) {
        const float* ga = A + (size_t)(m0 + lrow) * Hd + k0 + lcb;
        const float* gb = B + (size_t)(n0 + lrow) * Hd + k0 + lcb;
        #pragma unroll
        for (int j = 0; j < 8; j += 4) {
            float4 va = *(const float4*)(ga + j);
            float4 vb = *(const float4*)(gb + j);
            float av[4] = {va.x, va.y, va.z, va.w};
            float bv[4] = {vb.x, vb.y, vb.z, vb.w};
            #pragma unroll
            for (int u = 0; u < 4; ++u) {
                __nv_bfloat16 ha = __float2bfloat16(av[u]);
                sAh[lrow][lcb + j + u] = ha;
                sAl[lrow][lcb + j + u] = __float2bfloat16(av[u] - __bfloat162float(ha));
                __nv_bfloat16 hb = __float2bfloat16(bv[u]);
                sBh[lrow][lcb + j + u] = hb;
                sBl[lrow][lcb + j + u] = __float2bfloat16(bv[u] - __bfloat162float(hb));
            }
        }
        __syncthreads();

        #pragma unroll
        for (int p = 0; p < 3; ++p) {
            const __nv_bfloat16 (*aS)[40] = (p == 2) ? sAl : sAh;
            const __nv_bfloat16 (*bS)[40] = (p == 1) ? sBl : sBh;
            #pragma unroll
            for (int kk = 0; kk < 32; kk += 16) {
                wmma::fragment<wmma::matrix_a, 16, 16, 16, __nv_bfloat16, wmma::row_major> af;
                wmma::fragment<wmma::matrix_b, 16, 16, 16, __nv_bfloat16, wmma::col_major> bf;
                wmma::load_matrix_sync(bf, &bS[wn * 16][kk], 40);
                #pragma unroll
                for (int i = 0; i < 2; ++i) {
                    wmma::load_matrix_sync(af, &aS[wm * 32 + i * 16][kk], 40);
                    wmma::mma_sync(acc[i], af, bf, acc[i]);
                }
            }
        }
        __syncthreads();
    }

    wmma::store_matrix_sync(&sC[wm * 32][wn * 16], acc[0], 72, wmma::mem_row_major);
    wmma::store_matrix_sync(&sC[wm * 32 + 16][wn * 16], acc[1], 72, wmma::mem_row_major);
    __syncthreads();

    const float slope = slopes[1];
    #pragma unroll
    for (int it = 0; it < 16; ++it) {
        int idx = it * 256 + tid;
        int r = idx >> 6, c = idx & 63;
        const int q = m0 + r, kk = n0 + c;
        Pb[(size_t)q * Ss + kk] = sC[r][c] * 0.125f - slope * fabsf((float)(q - kk));
    }
}

// ---------------------------------------------------------------------------
// Head-aware V transpose (VALIDATED round 10).
// ---------------------------------------------------------------------------
__global__ void transpose_vh(const float* __restrict__ in, float* __restrict__ outT)
{
    __shared__ float t[32][33];
    const int b = blockIdx.z >> 4, h = blockIdx.z & 15;
    const int k0 = blockIdx.x * 32, d0 = blockIdx.y * 32;
    const int tx = threadIdx.x, ty = threadIdx.y;
    const float* src = in + (size_t)b * Ss * Ee + (size_t)h * Ss * Hd;  // (k, d), ld = Hd
    float* dst = outT + (size_t)b * Ee * Ss + (size_t)h * Hd * Ss;      // (d, k), ld = Ss
    #pragma unroll
    for (int i = 0; i < 32; i += 8)
        t[ty + i][tx] = src[(size_t)(k0 + ty + i) * Hd + d0 + tx];
    __syncthreads();
    #pragma unroll
    for (int i = 0; i < 32; i += 8)
        dst[(size_t)(d0 + ty + i) * Ss + k0 + tx] = t[tx][ty + i];
}

// ------------------------- softmax (round-1 proven) --------------------------
__global__ void softmax_kernel(float* __restrict__ P)
{
    float* r = P + (long)blockIdx.y * Ss * Ss + (long)blockIdx.x * Ss;
    const int tid = threadIdx.x;
    __shared__ float red[256];

    float vals[8];
    float m = -1e30f;
    #pragma unroll
    for (int i = 0; i < 8; i++) {
        vals[i] = r[tid + i * 256];
        m = fmaxf(m, vals[i]);
    }
    red[tid] = m;
    __syncthreads();
    for (int s = 128; s > 0; s >>= 1) {
        if (tid < s) red[tid] = fmaxf(red[tid], red[tid + s]);
        __syncthreads();
    }
    m = red[0];
    __syncthreads();

    float sum = 0.f;
    #pragma unroll
    for (int i = 0; i < 8; i++) {
        vals[i] = __expf(vals[i] - m);
        sum += vals[i];
    }
    red[tid] = sum;
    __syncthreads();
    for (int s = 128; s > 0; s >>= 1) {
        if (tid < s) red[tid] += red[tid + s];
        __syncthreads();
    }
    const float inv = 1.f / red[0];
    #pragma unroll
    for (int i = 0; i < 8; i++)
        r[tid + i * 256] = vals[i] * inv;
}

// ---------------------------------------------------------------------------
extern "C" void kernel_launch(void* const* d_in, const int* in_sizes, int n_in,
                              void* d_out, int out_size)
{
    const float* x      = (const float*)d_in[0];
    const float* Wq     = (const float*)d_in[1];
    const float* bq     = (const float*)d_in[2];
    const float* Wk     = (const float*)d_in[3];
    const float* bk     = (const float*)d_in[4];
    const float* Wv     = (const float*)d_in[5];
    const float* bv     = (const float*)d_in[6];
    const float* Wo     = (const float*)d_in[7];
    const float* bo     = (const float*)d_in[8];
    const float* slopes = (const float*)d_in[9];

    float* out = (float*)d_out;                 // (B, S, E)
    float* P   = out + (long)Bb * Ss * Ee;      // probs1 (B, 1, S, S), computed in place

    float *pQ1, *pK1, *pV, *pVt, *pAttn;
    cudaGetSymbolAddress((void**)&pQ1, g_Q1);
    cudaGetSymbolAddress((void**)&pK1, g_K1);
    cudaGetSymbolAddress((void**)&pV, g_V);
    cudaGetSymbolAddress((void**)&pVt, g_Vt);
    cudaGetSymbolAddress((void**)&pAttn, g_attn);

    // Head-1 Q/K projections: rows 128..255 per batch of x @ W^T.
    wsplit_gemm128<<<dim3(Ee / 128, 1, Bb), 256>>>(
        x + 128 * Ee, (long)Ss * Ee, Wq, 0, pQ1, (long)128 * Ee, Ee, bq, Ee, 0);
    wsplit_gemm128<<<dim3(Ee / 128, 1, Bb), 256>>>(
        x + 128 * Ee, (long)Ss * Ee, Wk, 0, pK1, (long)128 * Ee, Ee, bk, Ee, 0);

    // Head-1 scores + ALiBi (validated GEMM body).
    wsplit_scores<<<dim3(Ss / 64, Ss / 64, Bb), 256>>>(slopes, P);

    // Full V projection (launch #4 — ncu capture window).
    wsplit_gemm128<<<dim3(Ee / 128, Bb * Ss / 128, 1), 256>>>(
        x, 0, Wv, 0, pV, 0, Ee, bv, Ee, 0);

    // Softmax in place (into d_out probs region).
    softmax_kernel<<<dim3(Ss, Bb), 256>>>(P);

    // Head-aware transpose (validated).
    transpose_vh<<<dim3(Ss / 32, Hd / 32, Bb * Hh), dim3(32, 8)>>>(pV, pVt);

    // PV, storing head-flat directly (mode 1).
    wsplit_gemm128<<<dim3(Ee / 128, Ss / 128, Bb), 256>>>(
        P, (long)Ss * Ss, pVt, (long)Ee * Ss, pAttn, (long)Ss * Ee, 0, nullptr, Ss, 1);

    // Output projection.
    wsplit_gemm128<<<dim3(Ee / 128, Bb * Ss / 128, 1), 256>>>(
        pAttn, 0, Wo, 0, out, 0, Ee, bo, Ee, 0);
}

// round 16
// speedup vs baseline: 1.1279x; 1.1279x over previous
#include <cuda_runtime.h>
#include <cuda_bf16.h>
#include <mma.h>
#include <cstdint>

using namespace nvcuda;

#define Bb 2
#define Ss 2048
#define Ee 1024
#define Hh 16
#define Hd 64

// ------------------------- scratch (__device__ globals) ----------------------
__device__ float g_Q1[Bb * Ss * Hd];
__device__ float g_K1[Bb * Ss * Hd];
__device__ float g_V [Bb * Ss * Ee];     // V projection, flat (b, s, e)
__device__ float g_Vt[Bb * Ee * Ss];     // Vt[b][h*64+d][k] = V[b, h, k, d]
__device__ float g_attn[Bb * Ss * Ee];   // attn in flat (b, h, q, d) layout

// ---------------------------------------------------------------------------
// wmma split-bf16 NT GEMM, BM=128 x BN=64 x BK=32, in-kernel hi/lo split.
// 8 warps: 4(m) x 2(n); warp tile 32x32 (2x2 frags) -> mma/ldsm ratio 1.0.
// Fragment semantics = validated (A row_major [m][k] p40, B col_major [n][k] p40).
// Epilogue = direct-to-global store_matrix_sync + smem bias preload (R14-validated).
// mode 0: C[m*ldC+n].  mode 1: head-flat store (fragment stays inside one head).
// ---------------------------------------------------------------------------
__global__ void __launch_bounds__(256) wsplit_gemmW(
    const float* __restrict__ A, long Az,
    const float* __restrict__ B, long Bz,
    float* __restrict__ C, long Cz, int ldC,
    const float* __restrict__ bias, int K, int mode)
{
    __shared__ __align__(128) __nv_bfloat16 sAh[128][40];
    __shared__ __align__(128) __nv_bfloat16 sAl[128][40];
    __shared__ __align__(128) __nv_bfloat16 sBh[64][40];
    __shared__ __align__(128) __nv_bfloat16 sBl[64][40];

    const int tid = threadIdx.x, wid = tid >> 5;
    const int wm = wid & 3, wn = wid >> 2;
    const int m0 = blockIdx.y * 128, n0 = blockIdx.x * 64;
    A += (size_t)blockIdx.z * Az;
    B += (size_t)blockIdx.z * Bz;
    C += (size_t)blockIdx.z * Cz;

    wmma::fragment<wmma::accumulator, 16, 16, 16, float> acc[2][2];
    if (bias) {
        // Stage bias (16 rows replicated); preload accumulators (R14-validated).
        float* bstage = (float*)sAh;               // 16 x 72 floats = 4.6 KB
        #pragma unroll
        for (int it = 0; it < 4; ++it) {
            int idx = it * 256 + tid;              // 0..1023
            int r = idx >> 6, c = idx & 63;
            bstage[r * 72 + c] = bias[n0 + c];
        }
        __syncthreads();
        #pragma unroll
        for (int j = 0; j < 2; ++j) {
            wmma::load_matrix_sync(acc[0][j], bstage + wn * 32 + j * 16, 72,
                                   wmma::mem_row_major);
            acc[1][j] = acc[0][j];
        }
        __syncthreads();
    } else {
        #pragma unroll
        for (int i = 0; i < 2; ++i)
            #pragma unroll
            for (int j = 0; j < 2; ++j)
                wmma::fill_fragment(acc[i][j], 0.0f);
    }

    // Loaders (validated split patterns): A 128 rows x 32 cols, B 64 rows x 32 cols.
    const int lrow = tid >> 1, lcb = (tid & 1) * 16;   // A: 16 cols/thread
    const int brow = tid >> 2, bcb = (tid & 3) * 8;    // B: 8 cols/thread

    for (int k0 = 0; k0 < K; k0 += 32) {
        const float* ga = A + (size_t)(m0 + lrow) * K + k0 + lcb;
        const float* gb = B + (size_t)(n0 + brow) * K + k0 + bcb;
        #pragma unroll
        for (int j = 0; j < 16; j += 4) {
            float4 va = *(const float4*)(ga + j);
            float av[4] = {va.x, va.y, va.z, va.w};
            #pragma unroll
            for (int u = 0; u < 4; ++u) {
                __nv_bfloat16 ha = __float2bfloat16(av[u]);
                sAh[lrow][lcb + j + u] = ha;
                sAl[lrow][lcb + j + u] = __float2bfloat16(av[u] - __bfloat162float(ha));
            }
        }
        #pragma unroll
        for (int j = 0; j < 8; j += 4) {
            float4 vb = *(const float4*)(gb + j);
            float bv[4] = {vb.x, vb.y, vb.z, vb.w};
            #pragma unroll
            for (int u = 0; u < 4; ++u) {
                __nv_bfloat16 hb = __float2bfloat16(bv[u]);
                sBh[brow][bcb + j + u] = hb;
                sBl[brow][bcb + j + u] = __float2bfloat16(bv[u] - __bfloat162float(hb));
            }
        }
        __syncthreads();

        #pragma unroll
        for (int p = 0; p < 3; ++p) {
            const __nv_bfloat16 (*aS)[40] = (p == 2) ? sAl : sAh;
            const __nv_bfloat16 (*bS)[40] = (p == 1) ? sBl : sBh;
            #pragma unroll
            for (int kk = 0; kk < 32; kk += 16) {
                wmma::fragment<wmma::matrix_b, 16, 16, 16, __nv_bfloat16, wmma::col_major> bf[2];
                #pragma unroll
                for (int j = 0; j < 2; ++j)
                    wmma::load_matrix_sync(bf[j], &bS[wn * 32 + j * 16][kk], 40);
                #pragma unroll
                for (int i = 0; i < 2; ++i) {
                    wmma::fragment<wmma::matrix_a, 16, 16, 16, __nv_bfloat16, wmma::row_major> af;
                    wmma::load_matrix_sync(af, &aS[wm * 32 + i * 16][kk], 40);
                    #pragma unroll
                    for (int j = 0; j < 2; ++j)
                        wmma::mma_sync(acc[i][j], af, bf[j], acc[i][j]);
                }
            }
        }
        __syncthreads();
    }

    // Direct-to-global epilogue (R14-validated).
    #pragma unroll
    for (int i = 0; i < 2; ++i) {
        #pragma unroll
        for (int j = 0; j < 2; ++j) {
            const int mrow = m0 + wm * 32 + i * 16;
            const int ncol = n0 + wn * 32 + j * 16;
            if (mode == 0) {
                wmma::store_matrix_sync(&C[(size_t)mrow * ldC + ncol], acc[i][j],
                                        ldC, wmma::mem_row_major);
            } else {
                float* base = C + (size_t)(ncol >> 6) * (Ss * Hd)
                                + (size_t)mrow * Hd + (ncol & 63);
                wmma::store_matrix_sync(base, acc[i][j], Hd, wmma::mem_row_major);
            }
        }
    }
}

// ---------------------------------------------------------------------------
// wmma split-bf16 scores (VALIDATED round 13):
// P[q,k] = 0.125 * dot(Q1[q,:], K1[k,:]) - slope*|q-k|
// ---------------------------------------------------------------------------
__global__ void __launch_bounds__(256) wsplit_scores(
    const float* __restrict__ slopes, float* __restrict__ P)
{
    __shared__ __align__(128) __nv_bfloat16 sAh[64][40];
    __shared__ __align__(128) __nv_bfloat16 sAl[64][40];
    __shared__ __align__(128) __nv_bfloat16 sBh[64][40];
    __shared__ __align__(128) __nv_bfloat16 sBl[64][40];
    __shared__ __align__(128) float sC[64][72];

    const int tid = threadIdx.x, wid = tid >> 5;
    const int wm = wid & 1, wn = wid >> 1;
    const int m0 = blockIdx.y * 64, n0 = blockIdx.x * 64;
    const float* A = g_Q1 + (size_t)blockIdx.z * Ss * Hd;
    const float* B = g_K1 + (size_t)blockIdx.z * Ss * Hd;
    float* Pb = P + (size_t)blockIdx.z * Ss * Ss;

    const int lrow = tid >> 2, lcb = (tid & 3) * 8;

    wmma::fragment<wmma::accumulator, 16, 16, 16, float> acc[2];
    wmma::fill_fragment(acc[0], 0.0f);
    wmma::fill_fragment(acc[1], 0.0f);

    for (int k0 = 0; k0 < Hd; k0 += 32) {
        const float* ga = A + (size_t)(m0 + lrow) * Hd + k0 + lcb;
        const float* gb = B + (size_t)(n0 + lrow) * Hd + k0 + lcb;
        #pragma unroll
        for (int j = 0; j < 8; j += 4) {
            float4 va = *(const float4*)(ga + j);
            float4 vb = *(const float4*)(gb + j);
            float av[4] = {va.x, va.y, va.z, va.w};
            float bv[4] = {vb.x, vb.y, vb.z, vb.w};
            #pragma unroll
            for (int u = 0; u < 4; ++u) {
                __nv_bfloat16 ha = __float2bfloat16(av[u]);
                sAh[lrow][lcb + j + u] = ha;
                sAl[lrow][lcb + j + u] = __float2bfloat16(av[u] - __bfloat162float(ha));
                __nv_bfloat16 hb = __float2bfloat16(bv[u]);
                sBh[lrow][lcb + j + u] = hb;
                sBl[lrow][lcb + j + u] = __float2bfloat16(bv[u] - __bfloat162float(hb));
            }
        }
        __syncthreads();

        #pragma unroll
        for (int p = 0; p < 3; ++p) {
            const __nv_bfloat16 (*aS)[40] = (p == 2) ? sAl : sAh;
            const __nv_bfloat16 (*bS)[40] = (p == 1) ? sBl : sBh;
            #pragma unroll
            for (int kk = 0; kk < 32; kk += 16) {
                wmma::fragment<wmma::matrix_a, 16, 16, 16, __nv_bfloat16, wmma::row_major> af;
                wmma::fragment<wmma::matrix_b, 16, 16, 16, __nv_bfloat16, wmma::col_major> bf;
                wmma::load_matrix_sync(bf, &bS[wn * 16][kk], 40);
                #pragma unroll
                for (int i = 0; i < 2; ++i) {
                    wmma::load_matrix_sync(af, &aS[wm * 32 + i * 16][kk], 40);
                    wmma::mma_sync(acc[i], af, bf, acc[i]);
                }
            }
        }
        __syncthreads();
    }

    wmma::store_matrix_sync(&sC[wm * 32][wn * 16], acc[0], 72, wmma::mem_row_major);
    wmma::store_matrix_sync(&sC[wm * 32 + 16][wn * 16], acc[1], 72, wmma::mem_row_major);
    __syncthreads();

    const float slope = slopes[1];
    #pragma unroll
    for (int it = 0; it < 16; ++it) {
        int idx = it * 256 + tid;
        int r = idx >> 6, c = idx & 63;
        const int q = m0 + r, kk = n0 + c;
        Pb[(size_t)q * Ss + kk] = sC[r][c] * 0.125f - slope * fabsf((float)(q - kk));
    }
}

// ---------------------------------------------------------------------------
// Head-aware V transpose (VALIDATED round 10).
// ---------------------------------------------------------------------------
__global__ void transpose_vh(const float* __restrict__ in, float* __restrict__ outT)
{
    __shared__ float t[32][33];
    const int b = blockIdx.z >> 4, h = blockIdx.z & 15;
    const int k0 = blockIdx.x * 32, d0 = blockIdx.y * 32;
    const int tx = threadIdx.x, ty = threadIdx.y;
    const float* src = in + (size_t)b * Ss * Ee + (size_t)h * Ss * Hd;  // (k, d), ld = Hd
    float* dst = outT + (size_t)b * Ee * Ss + (size_t)h * Hd * Ss;      // (d, k), ld = Ss
    #pragma unroll
    for (int i = 0; i < 32; i += 8)
        t[ty + i][tx] = src[(size_t)(k0 + ty + i) * Hd + d0 + tx];
    __syncthreads();
    #pragma unroll
    for (int i = 0; i < 32; i += 8)
        dst[(size_t)(d0 + ty + i) * Ss + k0 + tx] = t[tx][ty + i];
}

// ------------------------- softmax (round-1 proven) --------------------------
__global__ void softmax_kernel(float* __restrict__ P)
{
    float* r = P + (long)blockIdx.y * Ss * Ss + (long)blockIdx.x * Ss;
    const int tid = threadIdx.x;
    __shared__ float red[256];

    float vals[8];
    float m = -1e30f;
    #pragma unroll
    for (int i = 0; i < 8; i++) {
        vals[i] = r[tid + i * 256];
        m = fmaxf(m, vals[i]);
    }
    red[tid] = m;
    __syncthreads();
    for (int s = 128; s > 0; s >>= 1) {
        if (tid < s) red[tid] = fmaxf(red[tid], red[tid + s]);
        __syncthreads();
    }
    m = red[0];
    __syncthreads();

    float sum = 0.f;
    #pragma unroll
    for (int i = 0; i < 8; i++) {
        vals[i] = __expf(vals[i] - m);
        sum += vals[i];
    }
    red[tid] = sum;
    __syncthreads();
    for (int s = 128; s > 0; s >>= 1) {
        if (tid < s) red[tid] += red[tid + s];
        __syncthreads();
    }
    const float inv = 1.f / red[0];
    #pragma unroll
    for (int i = 0; i < 8; i++)
        r[tid + i * 256] = vals[i] * inv;
}

// ---------------------------------------------------------------------------
extern "C" void kernel_launch(void* const* d_in, const int* in_sizes, int n_in,
                              void* d_out, int out_size)
{
    const float* x      = (const float*)d_in[0];
    const float* Wq     = (const float*)d_in[1];
    const float* bq     = (const float*)d_in[2];
    const float* Wk     = (const float*)d_in[3];
    const float* bk     = (const float*)d_in[4];
    const float* Wv     = (const float*)d_in[5];
    const float* bv     = (const float*)d_in[6];
    const float* Wo     = (const float*)d_in[7];
    const float* bo     = (const float*)d_in[8];
    const float* slopes = (const float*)d_in[9];

    float* out = (float*)d_out;                 // (B, S, E)
    float* P   = out + (long)Bb * Ss * Ee;      // probs1 (B, 1, S, S), computed in place

    float *pQ1, *pK1, *pV, *pVt, *pAttn;
    cudaGetSymbolAddress((void**)&pQ1, g_Q1);
    cudaGetSymbolAddress((void**)&pK1, g_K1);
    cudaGetSymbolAddress((void**)&pV, g_V);
    cudaGetSymbolAddress((void**)&pVt, g_Vt);
    cudaGetSymbolAddress((void**)&pAttn, g_attn);

    // Head-1 Q/K projections: rows 128..255 per batch of x @ W^T.
    wsplit_gemmW<<<dim3(Ee / 64, 1, Bb), 256>>>(
        x + 128 * Ee, (long)Ss * Ee, Wq, 0, pQ1, (long)128 * Ee, Ee, bq, Ee, 0);
    wsplit_gemmW<<<dim3(Ee / 64, 1, Bb), 256>>>(
        x + 128 * Ee, (long)Ss * Ee, Wk, 0, pK1, (long)128 * Ee, Ee, bk, Ee, 0);

    // Head-1 scores + ALiBi (validated GEMM body).
    wsplit_scores<<<dim3(Ss / 64, Ss / 64, Bb), 256>>>(slopes, P);

    // Full V projection (launch #4 — ncu capture window).
    wsplit_gemmW<<<dim3(Ee / 64, Bb * Ss / 128, 1), 256>>>(
        x, 0, Wv, 0, pV, 0, Ee, bv, Ee, 0);

    // Softmax in place (into d_out probs region).
    softmax_kernel<<<dim3(Ss, Bb), 256>>>(P);

    // Head-aware transpose (validated).
    transpose_vh<<<dim3(Ss / 32, Hd / 32, Bb * Hh), dim3(32, 8)>>>(pV, pVt);

    // PV, storing head-flat directly (mode 1).
    wsplit_gemmW<<<dim3(Ee / 64, Ss / 128, Bb), 256>>>(
        P, (long)Ss * Ss, pVt, (long)Ee * Ss, pAttn, (long)Ss * Ee, 0, nullptr, Ss, 1);

    // Output projection.
    wsplit_gemmW<<<dim3(Ee / 64, Bb * Ss / 128, 1), 256>>>(
        pAttn, 0, Wo, 0, out, 0, Ee, bo, Ee, 0);
}